// round 14
// baseline (speedup 1.0000x reference)
#include <cuda_runtime.h>
#include <cuda_fp16.h>
#include <math.h>
#include <stdint.h>

#define TAPS 16
#define ULEN 256
#define XLEN 1024
#define YLEN 256
#define NTOT 16384
#define NB   148

// ---- conv smem geometry ----
#define UROWS 143
#define UPITCH 264
#define USZ  (UROWS * UPITCH * 2)     // 75504
#define MBLK 8192                     // conv M block: 128 o-rows x 32 halves x 2B
#define MOFF (2 * USZ)                // 151008
#define CONV_MBAR (MOFF + 6 * MBLK)   // 200160
#define CONV_SMEM (CONV_MBAR + 64)

// ---- chain gemm smem: ring-3, KB=64, packed+swizzled 128B rows ----
#define CGA 16384                     // 128 rows x 64 halves x 2B
#define GSLOT (4 * CGA)               // Ah,Al,Bh,Bl = 65536
#define GRING 3
#define GEMM_MBAR (GRING * GSLOT)     // 196608
#define GEMM_SMEM (GEMM_MBAR + 64)
#define CSTAGES 16

#define PJH (YLEN * XLEN)

// ---------------- scratch (blocked/swizzled fp16 layouts) ----------------
__device__ __align__(128) __half g_Ah[XLEN * XLEN],  g_Al[XLEN * XLEN];
__device__ __align__(128) __half g_Ath[XLEN * XLEN], g_Atl[XLEN * XLEN];
__device__ __align__(128) __half g_S2h[XLEN * XLEN], g_S2l[XLEN * XLEN];
__device__ __align__(128) __half g_St2h[XLEN * XLEN], g_St2l[XLEN * XLEN];
__device__ __align__(128) __half g_S4h[XLEN * XLEN], g_S4l[XLEN * XLEN];
__device__ __align__(128) __half g_St4h[XLEN * XLEN], g_St4l[XLEN * XLEN];
__device__ __align__(128) __half g_St8h[XLEN * XLEN], g_St8l[XLEN * XLEN];
__device__ __align__(128) __half g_Ph[TAPS * PJH],   g_Pl[TAPS * PJH];
__device__ __align__(128) __half g_Bth[ULEN * XLEN], g_Btl[ULEN * XLEN];
__device__ __align__(128) float  g_Mall[TAPS * YLEN * ULEN];
__device__ __align__(128) __half g_Mhi[TAPS * 8 * 256 * 32];
__device__ __align__(128) __half g_Mlo[TAPS * 8 * 256 * 32];
__device__ unsigned g_sync;

// ---------------- helpers ----------------
__device__ __forceinline__ uint32_t smem_u32(const void* p) {
    uint32_t a;
    asm("{ .reg .u64 t; cvta.to.shared.u64 t, %1; cvt.u32.u64 %0, t; }" : "=r"(a) : "l"(p));
    return a;
}
__device__ __forceinline__ void ldsm4(uint32_t* r, uint32_t a) {
    asm volatile("ldmatrix.sync.aligned.m8n8.x4.shared.b16 {%0,%1,%2,%3}, [%4];"
                 : "=r"(r[0]), "=r"(r[1]), "=r"(r[2]), "=r"(r[3]) : "r"(a));
}
__device__ __forceinline__ void mma16816(float* c, const uint32_t* a, const uint32_t* b) {
    asm volatile(
        "mma.sync.aligned.m16n8k16.row.col.f32.f16.f16.f32 "
        "{%0,%1,%2,%3}, {%4,%5,%6,%7}, {%8,%9}, {%0,%1,%2,%3};"
        : "+f"(c[0]), "+f"(c[1]), "+f"(c[2]), "+f"(c[3])
        : "r"(a[0]), "r"(a[1]), "r"(a[2]), "r"(a[3]), "r"(b[0]), "r"(b[1]));
}
#define MB_INIT(mb, c)  asm volatile("mbarrier.init.shared.b64 [%0], %1;" :: "r"(mb), "r"(c) : "memory")
#define MB_EXPECT(mb, tx) asm volatile("mbarrier.arrive.expect_tx.shared.b64 _, [%0], %1;" :: "r"(mb), "r"(tx) : "memory")
#define BULK(dst, src, bytes, mb) \
    asm volatile("cp.async.bulk.shared::cta.global.mbarrier::complete_tx::bytes [%0], [%1], %2, [%3];" \
                 :: "r"(dst), "l"(src), "r"(bytes), "r"(mb) : "memory")
#define MB_WAIT(mb, ph) \
    asm volatile("{\n\t.reg .pred p;\n\tWL_%=:\n\t" \
        "mbarrier.try_wait.parity.acquire.cta.shared::cta.b64 p, [%0], %1;\n\t" \
        "@p bra.uni WD_%=;\n\tbra.uni WL_%=;\n\tWD_%=:\n\t}" \
        :: "r"(mb), "r"(ph) : "memory")
#define FENCE_PROXY() asm volatile("fence.proxy.async;" ::: "memory")

// blocked+swizzled element offset for a 1024-col fp16 matrix
__device__ __forceinline__ size_t blk(int row, int col) {
    int r = row & 127, cc = col & 63;
    int cp = (cc >> 3) ^ (r & 7);
    return ((size_t)((row >> 7) * 16 + (col >> 6)) * 128 + r) * 64 + cp * 8 + (cc & 7);
}
__device__ __forceinline__ void split_st(__half* H, __half* L, size_t off, float v) {
    __half h = __float2half_rn(v);
    H[off] = h;
    L[off] = __float2half_rn(v - __half2float(h));
}

// ---------------- chain compute: one 32-k chunk on packed+swizzled slot ----------
template <int NPASS>
__device__ __forceinline__ void chain_chunk(
    uint32_t Ab, uint32_t Bb, int lane, int wm, int wn,
    float acc[2][4][4], int kbase)
{
#pragma unroll
    for (int ks = 0; ks < 2; ks++) {
        uint32_t ah[2][4], al[2][4], bh[2][4], bl[2][4];
        int swz = lane & 7;
#pragma unroll
        for (int mi = 0; mi < 2; mi++) {
            int r = wm * 32 + mi * 16 + (lane & 15);
            int c = kbase + ks * 2 + (lane >> 4);
            uint32_t a = Ab + (uint32_t)(r * 128 + ((c ^ swz) * 16));
            ldsm4(ah[mi], a);
            if (NPASS == 3) ldsm4(al[mi], a + CGA);
        }
#pragma unroll
        for (int nh = 0; nh < 2; nh++) {
            int r = wn * 32 + nh * 16 + (lane & 7) + ((lane >> 4) << 3);
            int c = kbase + ks * 2 + ((lane >> 3) & 1);
            uint32_t b = Bb + (uint32_t)(r * 128 + ((c ^ swz) * 16));
            ldsm4(bh[nh], b);
            if (NPASS == 3) ldsm4(bl[nh], b + CGA);
        }
#pragma unroll
        for (int mi = 0; mi < 2; mi++)
#pragma unroll
            for (int ni = 0; ni < 4; ni++) {
                const uint32_t* fh = &bh[ni >> 1][(ni & 1) * 2];
                mma16816(acc[mi][ni], ah[mi], fh);
                if (NPASS == 3) {
                    const uint32_t* fl = &bl[ni >> 1][(ni & 1) * 2];
                    mma16816(acc[mi][ni], al[mi], fh);
                    mma16816(acc[mi][ni], ah[mi], fl);
                }
            }
    }
}

// ---------------- persistent chain GEMM ----------------
struct Job {
    const __half *Xh, *Xl, *Wh, *Wl;
    __half *Oh, *Ol;       // blocked fp16 hi/lo out (nullable)
    __half *Th, *Tl;       // transposed blocked fp16 hi/lo out (nullable)
    float  *Of;            // fp32 row-major out (nullable)
    int mt, nt, ldo, npass, round;
};
#define NJOBS 10
struct JobList { Job j[NJOBS]; };

template <int NPASS>
__device__ __forceinline__ void issue_chain(
    uint32_t sb, unsigned g, const __half* Xh, const __half* Xl,
    const __half* Wh, const __half* Wl, int m0, int n0, int s)
{
    uint32_t slot = sb + (g % GRING) * GSLOT;
    uint32_t mb = sb + GEMM_MBAR + (g % GRING) * 8;
    MB_EXPECT(mb, (NPASS == 3) ? 65536u : 32768u);
    const char* xs = (const char*)(Xh + (size_t)m0 * 1024 + (size_t)s * 8192);
    const char* ws = (const char*)(Wh + (size_t)n0 * 1024 + (size_t)s * 8192);
    BULK(slot,           xs, 16384u, mb);
    BULK(slot + 2 * CGA, ws, 16384u, mb);
    if (NPASS == 3) {
        const char* xl = (const char*)(Xl + (size_t)m0 * 1024 + (size_t)s * 8192);
        const char* wl = (const char*)(Wl + (size_t)n0 * 1024 + (size_t)s * 8192);
        BULK(slot + CGA,     xl, 16384u, mb);
        BULK(slot + 3 * CGA, wl, 16384u, mb);
    }
}

template <int NPASS>
__device__ __forceinline__ void gemm_body(
    const Job& jb, uint32_t sb, int tid, int lane, int wm, int wn,
    int m0, int n0, float acc[2][4][4], unsigned& gctr)
{
    if (tid == 0) {
        issue_chain<NPASS>(sb, gctr,     jb.Xh, jb.Xl, jb.Wh, jb.Wl, m0, n0, 0);
        issue_chain<NPASS>(sb, gctr + 1, jb.Xh, jb.Xl, jb.Wh, jb.Wl, m0, n0, 1);
    }
    for (int s = 0; s < CSTAGES; s++) {
        unsigned g = gctr + s;
        uint32_t mb = sb + GEMM_MBAR + (g % GRING) * 8;
        MB_WAIT(mb, (g / GRING) & 1);
        uint32_t base = sb + (g % GRING) * GSLOT;
        chain_chunk<NPASS>(base, base + 2 * CGA, lane, wm, wn, acc, 0);
        chain_chunk<NPASS>(base, base + 2 * CGA, lane, wm, wn, acc, 4);
        __syncthreads();
        if (s + 2 < CSTAGES && tid == 0)
            issue_chain<NPASS>(sb, g + 2, jb.Xh, jb.Xl, jb.Wh, jb.Wl, m0, n0, s + 2);
    }
    gctr += CSTAGES;
    __syncthreads();
}

__device__ __forceinline__ void do_epilogue(
    const Job& jb, char* smem, int tid, int lane, int wm, int wn,
    int m0, int n0, float acc[2][4][4])
{
    float* epi = (float*)smem;   // 128 x 129
#pragma unroll
    for (int mi = 0; mi < 2; mi++)
#pragma unroll
        for (int ni = 0; ni < 4; ni++) {
            int row = wm * 32 + mi * 16 + (lane >> 2);
            int col = wn * 32 + ni * 8 + ((lane & 3) << 1);
            epi[row * 129 + col]           = acc[mi][ni][0];
            epi[row * 129 + col + 1]       = acc[mi][ni][1];
            epi[(row + 8) * 129 + col]     = acc[mi][ni][2];
            epi[(row + 8) * 129 + col + 1] = acc[mi][ni][3];
        }
    __syncthreads();

    if (jb.Oh) {
        int r = tid >> 2, cb = (tid & 3) * 32;
#pragma unroll
        for (int c = 0; c < 32; c++)
            split_st(jb.Oh, jb.Ol, blk(m0 + r, n0 + cb + c), epi[r * 129 + cb + c]);
    }
    if (jb.Th) {
        int c = tid >> 2, rb = (tid & 3) * 32;
#pragma unroll
        for (int i = 0; i < 32; i++)
            split_st(jb.Th, jb.Tl, blk(n0 + c, m0 + rb + i), epi[(rb + i) * 129 + c]);
    }
    if (jb.Of) {
        int r = tid >> 2, cb = (tid & 3) * 32;
        float* op = jb.Of + (size_t)(m0 + r) * jb.ldo + n0 + cb;
        const float* sp = epi + r * 129 + cb;
#pragma unroll
        for (int i = 0; i < 8; i++)
            *(float4*)(op + i * 4) = make_float4(sp[i*4], sp[i*4+1], sp[i*4+2], sp[i*4+3]);
    }
    __syncthreads();
}

__global__ __launch_bounds__(512, 1)
void chain_pers(JobList jl)
{
    extern __shared__ char smem[];
    const uint32_t sb = smem_u32(smem);
    const int tid = threadIdx.x, lane = tid & 31, w = tid >> 5;
    const int wm = w >> 2, wn = w & 3;

    if (tid == 0)
#pragma unroll
        for (int i = 0; i < GRING; i++) MB_INIT(sb + GEMM_MBAR + i * 8, 1);
    __syncthreads();

    unsigned gctr = 0;
    for (int r = 1; r <= 5; r++) {
        int starts[NJOBS], total = 0;
#pragma unroll
        for (int q = 0; q < NJOBS; q++) {
            starts[q] = total;
            if (jl.j[q].round == r) total += jl.j[q].mt * jl.j[q].nt;
        }
        for (int g = blockIdx.x; g < total; g += NB) {
            int q = 0;
#pragma unroll
            for (int k = 0; k < NJOBS; k++)
                if (jl.j[k].round == r && g >= starts[k] &&
                    g < starts[k] + jl.j[k].mt * jl.j[k].nt) q = k;
            const Job& jb = jl.j[q];
            int t = g - starts[q];
            int m0 = (t / jb.nt) * 128, n0 = (t % jb.nt) * 128;
            float acc[2][4][4] = {};
            if (jb.npass == 3)
                gemm_body<3>(jb, sb, tid, lane, wm, wn, m0, n0, acc, gctr);
            else
                gemm_body<1>(jb, sb, tid, lane, wm, wn, m0, n0, acc, gctr);
            do_epilogue(jb, smem, tid, lane, wm, wn, m0, n0, acc);
        }
        __syncthreads();
        __threadfence();
        if (tid == 0) {
            atomicAdd(&g_sync, 1u);
            volatile unsigned* p = &g_sync;
            unsigned target = (unsigned)(r * NB);
            while (*p < target) { __nanosleep(64); }
        }
        __syncthreads();
        FENCE_PROXY();
        __threadfence();
    }
}

// ---------------- conv kernel: bulk M stream, 256 threads ----------------
__device__ __forceinline__ void conv_chunk(
    uint32_t aH, uint32_t aL, uint32_t Bb, int lane, int wn,
    float acc[4][4][4], bool threep)
{
    const uint32_t aoff = (uint32_t)(((lane & 15) * UPITCH + ((lane >> 4) << 3)) * 2);
#pragma unroll
    for (int ks = 0; ks < 2; ks++) {
        uint32_t ah[4][4], al[4][4], bh[2][4], bl[2][4];
#pragma unroll
        for (int mi = 0; mi < 4; mi++) {
            uint32_t a = aH + aoff + (uint32_t)((mi * 16 * UPITCH + ks * 16) * 2);
            ldsm4(ah[mi], a);
            if (threep) ldsm4(al[mi], a + (aL - aH));
        }
#pragma unroll
        for (int nh = 0; nh < 2; nh++) {
            int r = wn * 32 + nh * 16 + (lane & 7) + ((lane >> 4) << 3);
            int c = ks * 2 + ((lane >> 3) & 1);
            uint32_t b = Bb + (uint32_t)(r * 64 + ((c ^ (lane & 3)) * 16));
            ldsm4(bh[nh], b);
            if (threep) ldsm4(bl[nh], b + MBLK);
        }
#pragma unroll
        for (int mi = 0; mi < 4; mi++)
#pragma unroll
            for (int ni = 0; ni < 4; ni++) {
                const uint32_t* fh = &bh[ni >> 1][(ni & 1) * 2];
                mma16816(acc[mi][ni], ah[mi], fh);
                if (threep) {
                    const uint32_t* fl = &bl[ni >> 1][(ni & 1) * 2];
                    mma16816(acc[mi][ni], al[mi], fh);
                    mma16816(acc[mi][ni], ah[mi], fl);
                }
            }
    }
}

__device__ __forceinline__ void issue_conv(
    uint32_t sb, const __half* Mh, const __half* Ml, int s, int o0)
{
    uint32_t slot = sb + MOFF + (uint32_t)(s % 3) * 2 * MBLK;
    uint32_t mb = sb + CONV_MBAR + (s % 3) * 8;
    bool lo = (s >> 3) < 2;
    MB_EXPECT(mb, lo ? 16384u : 8192u);
    const char* src = (const char*)(Mh + ((size_t)s * 256 + o0) * 32);
    BULK(slot, src, 8192u, mb);
    if (lo) {
        const char* srl = (const char*)(Ml + ((size_t)s * 256 + o0) * 32);
        BULK(slot + MBLK, srl, 8192u, mb);
    }
}

__device__ __forceinline__ void split2(float x, float y, uint32_t& hi, uint32_t& lo) {
    __half hx = __float2half_rn(x), hy = __float2half_rn(y);
    __half2 h; h.x = hx; h.y = hy;
    __half2 l; l.x = __float2half_rn(x - __half2float(hx));
    l.y = __float2half_rn(y - __half2float(hy));
    hi = *(uint32_t*)&h; lo = *(uint32_t*)&l;
}

__global__ __launch_bounds__(256, 1)
void conv_mma(const float* __restrict__ u, const __half* __restrict__ Mh,
              const __half* __restrict__ Ml, float* __restrict__ out)
{
    extern __shared__ char smem[];
    const uint32_t sb = smem_u32(smem);
    const int tid = threadIdx.x, lane = tid & 31, w = tid >> 5;
    const int wm = w >> 2, wn = w & 3;
    const int n0 = blockIdx.x * 128;
    const int o0 = blockIdx.y * 128;

    if (tid == 0) {
#pragma unroll
        for (int i = 0; i < 3; i++) MB_INIT(sb + CONV_MBAR + i * 8, 1);
        issue_conv(sb, Mh, Ml, 0, o0);
        issue_conv(sb, Mh, Ml, 1, o0);
    }

    for (int i = tid; i < UROWS * 64; i += 256) {
        int r = i >> 6, c4 = i & 63;
        int n = n0 - (TAPS - 1) + r;
        float4 v = make_float4(0.f, 0.f, 0.f, 0.f);
        if (n >= 0 && n < NTOT) v = *(const float4*)(u + (size_t)n * ULEN + c4 * 4);
        uint32_t h0, l0, h1, l1;
        split2(v.x, v.y, h0, l0);
        split2(v.z, v.w, h1, l1);
        uint32_t base = (uint32_t)((r * UPITCH + c4 * 4) * 2);
        *(uint2*)(smem + base)       = make_uint2(h0, h1);
        *(uint2*)(smem + USZ + base) = make_uint2(l0, l1);
    }
    __syncthreads();

    float acc[4][4][4] = {};
    const int S = TAPS * 8;
    for (int s = 0; s < S; s++) {
        uint32_t mb = sb + CONV_MBAR + (s % 3) * 8;
        MB_WAIT(mb, (s / 3) & 1);
        int j = s >> 3, kc = s & 7;
        uint32_t aH = sb + (uint32_t)(((((TAPS - 1) - j) + wm * 64) * UPITCH + kc * 32) * 2);
        uint32_t aL = aH + USZ;
        uint32_t Bb = sb + MOFF + (uint32_t)(s % 3) * 2 * MBLK;
        conv_chunk(aH, aL, Bb, lane, wn, acc, j < 2);
        __syncthreads();
        if (s + 2 < S && tid == 0)
            issue_conv(sb, Mh, Ml, s + 2, o0);
    }
    __syncthreads();

    float* epi = (float*)smem;   // 128 x 132
#pragma unroll
    for (int mi = 0; mi < 4; mi++)
#pragma unroll
        for (int ni = 0; ni < 4; ni++) {
            int row = wm * 64 + mi * 16 + (lane >> 2);
            int col = wn * 32 + ni * 8 + ((lane & 3) << 1);
            epi[col * 132 + row]           = tanhf(acc[mi][ni][0]);
            epi[(col + 1) * 132 + row]     = tanhf(acc[mi][ni][1]);
            epi[col * 132 + row + 8]       = tanhf(acc[mi][ni][2]);
            epi[(col + 1) * 132 + row + 8] = tanhf(acc[mi][ni][3]);
        }
    __syncthreads();
    {
        int r = tid >> 1, half = tid & 1;
        float* dst = out + (size_t)(o0 + r) * NTOT + n0 + half * 64;
        const float* src = epi + r * 132 + half * 64;
#pragma unroll
        for (int i = 0; i < 16; i++)
            *(float4*)(dst + i * 4) = *(const float4*)(src + i * 4);
    }
}

// ---------------- split + transpose-split into blocked/swizzled layout -----------
__global__ void split_tr(const float* __restrict__ in, __half* oh, __half* ol,
                         __half* th, __half* tl, int R, int Cc)
{
    __shared__ float ts[32][33];
    int c0 = blockIdx.x << 5, r0 = blockIdx.y << 5;
    int lx = threadIdx.x, ly = threadIdx.y;
    for (int i = ly; i < 32; i += 8)
        ts[i][lx] = in[(size_t)(r0 + i) * Cc + c0 + lx];
    __syncthreads();
    if (oh)
        for (int i = ly; i < 32; i += 8)
            split_st(oh, ol, blk(r0 + i, c0 + lx), ts[i][lx]);
    if (th)
        for (int i = ly; i < 32; i += 8)
            split_st(th, tl, blk(c0 + i, r0 + lx), ts[lx][i]);
}

__global__ void build_mtb(const float* __restrict__ Mall, const float* __restrict__ D,
                          __half* __restrict__ Mh, __half* __restrict__ Ml)
{
    int idx = blockIdx.x * 256 + threadIdx.x;
    int k = idx & 255, o = (idx >> 8) & 255, j = idx >> 16;
    float v = Mall[(size_t)((j << 8) + o) * ULEN + k];
    if (j == 0) v += D[(o << 8) + k];
    __half h = __float2half_rn(v);
    __half l = __float2half_rn(v - __half2float(h));
    int kc = k >> 5, ki = k & 31;
    int kis = (((ki >> 3) ^ (o & 3)) << 3) | (ki & 7);   // 4-chunk XOR swizzle
    size_t dst = ((size_t)(j * 8 + kc) * 256 + o) * 32 + kis;
    Mh[dst] = h;
    Ml[dst] = l;
}

// ---------------- launcher ----------------
extern "C" void kernel_launch(void* const* d_in, const int* in_sizes, int n_in,
                              void* d_out, int out_size)
{
    const float* u  = (const float*)d_in[0];
    const float* A  = (const float*)d_in[1];
    const float* B  = (const float*)d_in[2];
    const float* Cm = (const float*)d_in[3];
    const float* D  = (const float*)d_in[4];

    __half *Ah, *Al, *Ath, *Atl, *S2h, *S2l, *St2h, *St2l, *S4h, *S4l, *St4h, *St4l;
    __half *St8h, *St8l, *Ph, *Pl, *Bth, *Btl, *Mhi, *Mlo;
    float *Mall;
    void* syncp;
    cudaGetSymbolAddress((void**)&Ah,   g_Ah);   cudaGetSymbolAddress((void**)&Al,   g_Al);
    cudaGetSymbolAddress((void**)&Ath,  g_Ath);  cudaGetSymbolAddress((void**)&Atl,  g_Atl);
    cudaGetSymbolAddress((void**)&S2h,  g_S2h);  cudaGetSymbolAddress((void**)&S2l,  g_S2l);
    cudaGetSymbolAddress((void**)&St2h, g_St2h); cudaGetSymbolAddress((void**)&St2l, g_St2l);
    cudaGetSymbolAddress((void**)&S4h,  g_S4h);  cudaGetSymbolAddress((void**)&S4l,  g_S4l);
    cudaGetSymbolAddress((void**)&St4h, g_St4h); cudaGetSymbolAddress((void**)&St4l, g_St4l);
    cudaGetSymbolAddress((void**)&St8h, g_St8h); cudaGetSymbolAddress((void**)&St8l, g_St8l);
    cudaGetSymbolAddress((void**)&Ph,   g_Ph);   cudaGetSymbolAddress((void**)&Pl,   g_Pl);
    cudaGetSymbolAddress((void**)&Bth,  g_Bth);  cudaGetSymbolAddress((void**)&Btl,  g_Btl);
    cudaGetSymbolAddress((void**)&Mall, g_Mall);
    cudaGetSymbolAddress((void**)&Mhi,  g_Mhi);  cudaGetSymbolAddress((void**)&Mlo,  g_Mlo);
    cudaGetSymbolAddress(&syncp, g_sync);

    cudaFuncSetAttribute(conv_mma,   cudaFuncAttributeMaxDynamicSharedMemorySize, CONV_SMEM);
    cudaFuncSetAttribute(chain_pers, cudaFuncAttributeMaxDynamicSharedMemorySize, GEMM_SMEM);

    split_tr<<<dim3(32, 32), dim3(32, 8)>>>(A,  Ah, Al, Ath, Atl, XLEN, XLEN);
    split_tr<<<dim3(32, 8),  dim3(32, 8)>>>(Cm, Ph, Pl, nullptr, nullptr, YLEN, XLEN);
    split_tr<<<dim3(8, 32),  dim3(32, 8)>>>(B,  nullptr, nullptr, Bth, Btl, XLEN, ULEN);

    cudaMemsetAsync(syncp, 0, sizeof(unsigned));

    JobList jl = {{
        // r1: S2 (+St2) = A@A [1p];  P1 = C@A [3p]
        {Ah, Al, Ath, Atl, S2h, S2l, St2h, St2l, nullptr, 8, 8, 0, 1, 1},
        {Ph, Pl, Ath, Atl, Ph + PJH, Pl + PJH, nullptr, nullptr, nullptr, 2, 8, 0, 3, 1},
        // r2: S4 (+St4) = S2@S2 [1p];  P[2:4] = P[0:2]@A2 [1p]
        {S2h, S2l, St2h, St2l, S4h, S4l, St4h, St4l, nullptr, 8, 8, 0, 1, 2},
        {Ph, Pl, St2h, St2l, Ph + 2 * PJH, Pl + 2 * PJH, nullptr, nullptr, nullptr, 4, 8, 0, 1, 2},
        // r3: St8 = (S4@S4)^T [1p];  P[4:8] = P[0:4]@A4 [1p];  Mall[0:2] = P[0:2]@B [3p]
        {S4h, S4l, St4h, St4l, nullptr, nullptr, St8h, St8l, nullptr, 8, 8, 0, 1, 3},
        {Ph, Pl, St4h, St4l, Ph + 4 * PJH, Pl + 4 * PJH, nullptr, nullptr, nullptr, 8, 8, 0, 1, 3},
        {Ph, Pl, Bth, Btl, nullptr, nullptr, nullptr, nullptr, Mall, 4, 2, ULEN, 3, 3},
        // r4: P[8:16] = P[0:8]@A8 [1p];  Mall[2:8] = P[2:8]@B [1p]
        {Ph, Pl, St8h, St8l, Ph + 8 * PJH, Pl + 8 * PJH, nullptr, nullptr, nullptr, 16, 8, 0, 1, 4},
        {Ph + 2 * PJH, Pl + 2 * PJH, Bth, Btl, nullptr, nullptr, nullptr, nullptr,
         Mall + 2 * YLEN * ULEN, 12, 2, ULEN, 1, 4},
        // r5: Mall[8:16] = P[8:16]@B [1p]
        {Ph + 8 * PJH, Pl + 8 * PJH, Bth, Btl, nullptr, nullptr, nullptr, nullptr,
         Mall + 8 * YLEN * ULEN, 16, 2, ULEN, 1, 5},
    }};

    chain_pers<<<NB, 512, GEMM_SMEM>>>(jl);

    build_mtb<<<(TAPS * YLEN * ULEN) / 256, 256>>>(Mall, D, Mhi, Mlo);

    conv_mma<<<dim3(NTOT / 128, 2), 256, CONV_SMEM>>>(u, Mhi, Mlo, (float*)d_out);
}

// round 16
// speedup vs baseline: 1.7031x; 1.7031x over previous
#include <cuda_runtime.h>
#include <cuda_fp16.h>
#include <math.h>
#include <stdint.h>

#define TAPS 16
#define ULEN 256
#define XLEN 1024
#define YLEN 256
#define NTOT 16384
#define NB   148

// ---- conv smem geometry (exact R12) ----
#define UROWS 143
#define UPITCH 264
#define USZ  (UROWS * UPITCH * 2)
#define MPITCH 40
#define MSTG (128 * MPITCH * 2)
#define MOFF (2 * USZ)
#define CONV_SMEM (MOFF + 6 * MSTG)   // 212448

// ---- chain gemm smem: ring-3 bulk slots, KB=64 packed 128B rows ----
#define CGA 16384                      // 128 rows x 64 halves x 2B
#define GSLOT (4 * CGA)                // XH,XL,WH,WL = 65536
#define GRING 3
#define GEMM_MBAR (GRING * GSLOT)      // 196608
#define GEMM_SMEM (GEMM_MBAR + 64)
#define CSTAGES 16

#define PJH (YLEN * XLEN)

// ---------------- scratch ----------------
__device__ __align__(128) __half g_Ah[XLEN * XLEN],  g_Al[XLEN * XLEN];
__device__ __align__(128) __half g_Ath[XLEN * XLEN], g_Atl[XLEN * XLEN];
__device__ __align__(128) __half g_S2h[XLEN * XLEN], g_S2l[XLEN * XLEN];
__device__ __align__(128) __half g_St2h[XLEN * XLEN], g_St2l[XLEN * XLEN];
__device__ __align__(128) __half g_S4h[XLEN * XLEN], g_S4l[XLEN * XLEN];
__device__ __align__(128) __half g_St4h[XLEN * XLEN], g_St4l[XLEN * XLEN];
__device__ __align__(128) __half g_St8h[XLEN * XLEN], g_St8l[XLEN * XLEN];
__device__ __align__(128) __half g_Ph[TAPS * PJH],   g_Pl[TAPS * PJH];
__device__ __align__(128) __half g_Bth[ULEN * XLEN], g_Btl[ULEN * XLEN];
__device__ __align__(128) float  g_Mall[TAPS * YLEN * ULEN];
__device__ __align__(128) __half g_Mhi[TAPS * 8 * 256 * 32];
__device__ __align__(128) __half g_Mlo[TAPS * 8 * 256 * 32];
__device__ unsigned g_sync;

// ---------------- helpers ----------------
__device__ __forceinline__ uint32_t smem_u32(const void* p) {
    uint32_t a;
    asm("{ .reg .u64 t; cvta.to.shared.u64 t, %1; cvt.u32.u64 %0, t; }" : "=r"(a) : "l"(p));
    return a;
}
__device__ __forceinline__ void split2(float x, float y, uint32_t& hi, uint32_t& lo) {
    __half hx = __float2half_rn(x), hy = __float2half_rn(y);
    __half2 h; h.x = hx; h.y = hy;
    __half2 l; l.x = __float2half_rn(x - __half2float(hx));
    l.y = __float2half_rn(y - __half2float(hy));
    hi = *(uint32_t*)&h; lo = *(uint32_t*)&l;
}
__device__ __forceinline__ void ldsm4(uint32_t* r, uint32_t a) {
    asm volatile("ldmatrix.sync.aligned.m8n8.x4.shared.b16 {%0,%1,%2,%3}, [%4];"
                 : "=r"(r[0]), "=r"(r[1]), "=r"(r[2]), "=r"(r[3]) : "r"(a));
}
__device__ __forceinline__ void mma16816(float* c, const uint32_t* a, const uint32_t* b) {
    asm volatile(
        "mma.sync.aligned.m16n8k16.row.col.f32.f16.f16.f32 "
        "{%0,%1,%2,%3}, {%4,%5,%6,%7}, {%8,%9}, {%0,%1,%2,%3};"
        : "+f"(c[0]), "+f"(c[1]), "+f"(c[2]), "+f"(c[3])
        : "r"(a[0]), "r"(a[1]), "r"(a[2]), "r"(a[3]), "r"(b[0]), "r"(b[1]));
}
#define CP16(dst, src) asm volatile("cp.async.cg.shared.global [%0], [%1], 16;" :: "r"(dst), "l"(src))
#define CPCOMMIT()     asm volatile("cp.async.commit_group;" ::: "memory")
#define CPWAIT1()      asm volatile("cp.async.wait_group 1;" ::: "memory")
#define CPWAIT0()      asm volatile("cp.async.wait_group 0;" ::: "memory")
#define MB_INIT(mb, c)  asm volatile("mbarrier.init.shared.b64 [%0], %1;" :: "r"(mb), "r"(c) : "memory")
#define MB_EXPECT(mb, tx) asm volatile("mbarrier.arrive.expect_tx.shared.b64 _, [%0], %1;" :: "r"(mb), "r"(tx) : "memory")
#define BULK(dst, src, bytes, mb) \
    asm volatile("cp.async.bulk.shared::cta.global.mbarrier::complete_tx::bytes [%0], [%1], %2, [%3];" \
                 :: "r"(dst), "l"(src), "r"(bytes), "r"(mb) : "memory")
#define MB_WAIT(mb, ph) \
    asm volatile("{\n\t.reg .pred p;\n\tWL_%=:\n\t" \
        "mbarrier.try_wait.parity.acquire.cta.shared::cta.b64 p, [%0], %1;\n\t" \
        "@p bra.uni WD_%=;\n\tbra.uni WL_%=;\n\tWD_%=:\n\t}" \
        :: "r"(mb), "r"(ph) : "memory")
#define FENCE_PROXY() asm volatile("fence.proxy.async;" ::: "memory")

// ---------------- generic compute (conv, R12) ----------------
template <int NPASS, int MI>
__device__ __forceinline__ void compute_stage(
    uint32_t aH, uint32_t aL, uint32_t bH, uint32_t bL,
    int lane, int wn, float acc[][4][4], int apitch)
{
    const uint32_t aoff = (uint32_t)(((lane & 15) * apitch + ((lane >> 4) << 3)) * 2);
    const uint32_t boff = (uint32_t)((((lane & 7) + ((lane >> 4) << 3)) * MPITCH +
                                      (((lane >> 3) & 1) << 3)) * 2);
    const uint32_t dAL = aL - aH, dBL = bL - bH;
#pragma unroll
    for (int ks = 0; ks < 2; ks++) {
        uint32_t ah[MI][4], al[MI][4], bh[2][4], bl[2][4];
#pragma unroll
        for (int mi = 0; mi < MI; mi++) {
            uint32_t a = aH + aoff + (uint32_t)((mi * 16 * apitch + ks * 16) * 2);
            ldsm4(ah[mi], a);
            if (NPASS == 3) ldsm4(al[mi], a + dAL);
        }
#pragma unroll
        for (int nh = 0; nh < 2; nh++) {
            uint32_t b = bH + boff + (uint32_t)(((wn * 32 + nh * 16) * MPITCH + ks * 16) * 2);
            ldsm4(bh[nh], b);
            if (NPASS == 3) ldsm4(bl[nh], b + dBL);
        }
#pragma unroll
        for (int mi = 0; mi < MI; mi++)
#pragma unroll
            for (int ni = 0; ni < 4; ni++) {
                const uint32_t* fh = &bh[ni >> 1][(ni & 1) * 2];
                mma16816(acc[mi][ni], ah[mi], fh);
                if (NPASS == 3) {
                    const uint32_t* fl = &bl[ni >> 1][(ni & 1) * 2];
                    mma16816(acc[mi][ni], al[mi], fh);
                    mma16816(acc[mi][ni], ah[mi], fl);
                }
            }
    }
}

// ---------------- chain compute: 64-k packed slot, XOR-swizzled chunks ----------
template <int NPASS>
__device__ __forceinline__ void chain_stage(
    uint32_t base, int lane, int wm, int wn, float acc[2][4][4])
{
#pragma unroll
    for (int ks = 0; ks < 4; ks++) {
        uint32_t ah[2][4], al[2][4], bh[2][4], bl[2][4];
#pragma unroll
        for (int mi = 0; mi < 2; mi++) {
            int r = wm * 32 + mi * 16 + (lane & 15);
            int c = ks * 2 + (lane >> 4);
            uint32_t a = base + (uint32_t)(r * 128 + ((c ^ (r & 7)) << 4));
            ldsm4(ah[mi], a);
            if (NPASS == 3) ldsm4(al[mi], a + CGA);
        }
#pragma unroll
        for (int nh = 0; nh < 2; nh++) {
            int r = wn * 32 + nh * 16 + (lane & 7) + ((lane >> 4) << 3);
            int c = ks * 2 + ((lane >> 3) & 1);
            uint32_t b = base + 2 * CGA + (uint32_t)(r * 128 + ((c ^ (r & 7)) << 4));
            ldsm4(bh[nh], b);
            if (NPASS == 3) ldsm4(bl[nh], b + CGA);
        }
#pragma unroll
        for (int mi = 0; mi < 2; mi++)
#pragma unroll
            for (int ni = 0; ni < 4; ni++) {
                const uint32_t* fh = &bh[ni >> 1][(ni & 1) * 2];
                mma16816(acc[mi][ni], ah[mi], fh);
                if (NPASS == 3) {
                    const uint32_t* fl = &bl[ni >> 1][(ni & 1) * 2];
                    mma16816(acc[mi][ni], al[mi], fh);
                    mma16816(acc[mi][ni], ah[mi], fl);
                }
            }
    }
}

// ---------------- persistent chain GEMM ----------------
struct Job {
    const __half *Xh, *Xl, *Wh, *Wl;
    __half *Oh, *Ol;
    __half *Th, *Tl;
    float  *Of;
    int mt, nt, ldo, npass, round;
};
#define NJOBS 10
struct JobList { Job j[NJOBS]; };

template <int NPASS>
__device__ __forceinline__ void issue_chain(
    uint32_t sb, unsigned g, const Job& jb, int m0, int n0, int s)
{
    uint32_t slot = sb + (g % GRING) * GSLOT;
    uint32_t mb = sb + GEMM_MBAR + (g % GRING) * 8;
    MB_EXPECT(mb, (NPASS == 3) ? 65536u : 32768u);
    const char* xs = (const char*)(jb.Xh + ((size_t)(m0 >> 7) * 16 + s) * 8192);
    const char* ws = (const char*)(jb.Wh + ((size_t)(n0 >> 7) * 16 + s) * 8192);
    BULK(slot,           xs, 16384u, mb);
    BULK(slot + 2 * CGA, ws, 16384u, mb);
    if (NPASS == 3) {
        const char* xl = (const char*)(jb.Xl + ((size_t)(m0 >> 7) * 16 + s) * 8192);
        const char* wl = (const char*)(jb.Wl + ((size_t)(n0 >> 7) * 16 + s) * 8192);
        BULK(slot + CGA,     xl, 16384u, mb);
        BULK(slot + 3 * CGA, wl, 16384u, mb);
    }
}

template <int NPASS>
__device__ __forceinline__ void gemm_body(
    const Job& jb, uint32_t sb, int tid, int lane, int wm, int wn,
    int m0, int n0, float acc[2][4][4], unsigned& gctr)
{
    if (tid == 0) {
        issue_chain<NPASS>(sb, gctr,     jb, m0, n0, 0);
        issue_chain<NPASS>(sb, gctr + 1, jb, m0, n0, 1);
    }
    for (int s = 0; s < CSTAGES; s++) {
        unsigned g = gctr + s;
        uint32_t mb = sb + GEMM_MBAR + (g % GRING) * 8;
        MB_WAIT(mb, (g / GRING) & 1);
        chain_stage<NPASS>(sb + (g % GRING) * GSLOT, lane, wm, wn, acc);
        __syncthreads();
        if (s + 2 < CSTAGES && tid == 0)
            issue_chain<NPASS>(sb, g + 2, jb, m0, n0, s + 2);
    }
    gctr += CSTAGES;
}

__device__ __forceinline__ void do_epilogue(
    const Job& jb, char* smem, int tid, int lane, int wm, int wn,
    int m0, int n0, float acc[2][4][4])
{
    float* epi = (float*)smem;   // 128 x 129
#pragma unroll
    for (int mi = 0; mi < 2; mi++)
#pragma unroll
        for (int ni = 0; ni < 4; ni++) {
            int row = wm * 32 + mi * 16 + (lane >> 2);
            int col = wn * 32 + ni * 8 + ((lane & 3) << 1);
            epi[row * 129 + col]           = acc[mi][ni][0];
            epi[row * 129 + col + 1]       = acc[mi][ni][1];
            epi[(row + 8) * 129 + col]     = acc[mi][ni][2];
            epi[(row + 8) * 129 + col + 1] = acc[mi][ni][3];
        }
    __syncthreads();

    if (jb.Oh) {
        size_t strip = (size_t)(m0 >> 7) * 16 + (n0 >> 6);
#pragma unroll
        for (int q = 0; q < 4; q++) {
            int idx = q * 512 + tid;              // 0..2047
            int kb = idx >> 10, rem = idx & 1023;
            int r = rem >> 3, ch = rem & 7;
            const float* sp = epi + r * 129 + kb * 64 + ch * 8;
            uint32_t h[4], l[4];
#pragma unroll
            for (int e = 0; e < 4; e++) split2(sp[2 * e], sp[2 * e + 1], h[e], l[e]);
            size_t off = (strip + kb) * 8192 + (size_t)r * 64 + ((ch ^ (r & 7)) << 3);
            *(uint4*)(jb.Oh + off) = make_uint4(h[0], h[1], h[2], h[3]);
            *(uint4*)(jb.Ol + off) = make_uint4(l[0], l[1], l[2], l[3]);
        }
    }
    if (jb.Th) {
        size_t strip = (size_t)(n0 >> 7) * 16 + (m0 >> 6);
#pragma unroll
        for (int q = 0; q < 4; q++) {
            int idx = q * 512 + tid;
            int kb = idx >> 10, rem = idx & 1023;
            int j = rem >> 3, ch = rem & 7;
            uint32_t h[4], l[4];
#pragma unroll
            for (int e = 0; e < 4; e++) {
                float v0 = epi[(kb * 64 + ch * 8 + 2 * e) * 129 + j];
                float v1 = epi[(kb * 64 + ch * 8 + 2 * e + 1) * 129 + j];
                split2(v0, v1, h[e], l[e]);
            }
            size_t off = (strip + kb) * 8192 + (size_t)j * 64 + ((ch ^ (j & 7)) << 3);
            *(uint4*)(jb.Th + off) = make_uint4(h[0], h[1], h[2], h[3]);
            *(uint4*)(jb.Tl + off) = make_uint4(l[0], l[1], l[2], l[3]);
        }
    }
    if (jb.Of) {
        int r = tid >> 2, cb = (tid & 3) * 32;
        float* op = jb.Of + (size_t)(m0 + r) * jb.ldo + n0 + cb;
        const float* sp = epi + r * 129 + cb;
#pragma unroll
        for (int i = 0; i < 8; i++)
            *(float4*)(op + i * 4) = make_float4(sp[i*4], sp[i*4+1], sp[i*4+2], sp[i*4+3]);
    }
    __syncthreads();
}

__global__ __launch_bounds__(512, 1)
void chain_pers(JobList jl)
{
    extern __shared__ char smem[];
    const uint32_t sb = smem_u32(smem);
    const int tid = threadIdx.x, lane = tid & 31, w = tid >> 5;
    const int wm = w >> 2, wn = w & 3;

    if (tid == 0)
#pragma unroll
        for (int i = 0; i < GRING; i++) MB_INIT(sb + GEMM_MBAR + i * 8, 1);
    __syncthreads();

    unsigned gctr = 0;
    for (int r = 1; r <= 5; r++) {
        int starts[NJOBS], total = 0;
#pragma unroll
        for (int q = 0; q < NJOBS; q++) {
            starts[q] = total;
            if (jl.j[q].round == r) total += jl.j[q].mt * jl.j[q].nt;
        }
        for (int g = blockIdx.x; g < total; g += NB) {
            int q = 0;
#pragma unroll
            for (int k = 0; k < NJOBS; k++)
                if (jl.j[k].round == r && g >= starts[k] &&
                    g < starts[k] + jl.j[k].mt * jl.j[k].nt) q = k;
            const Job& jb = jl.j[q];
            int t = g - starts[q];
            int m0 = (t / jb.nt) * 128, n0 = (t % jb.nt) * 128;
            float acc[2][4][4] = {};
            if (jb.npass == 3)
                gemm_body<3>(jb, sb, tid, lane, wm, wn, m0, n0, acc, gctr);
            else
                gemm_body<1>(jb, sb, tid, lane, wm, wn, m0, n0, acc, gctr);
            do_epilogue(jb, smem, tid, lane, wm, wn, m0, n0, acc);
        }
        __syncthreads();
        __threadfence();
        if (tid == 0) {
            atomicAdd(&g_sync, 1u);
            volatile unsigned* p = &g_sync;
            unsigned target = (unsigned)(r * NB);
            while (*p < target) { __nanosleep(64); }
        }
        __syncthreads();
        FENCE_PROXY();
        __threadfence();
    }
}

// ---------------- conv kernel: EXACT R12 ----------------
__device__ __forceinline__ void issue_m(uint32_t sb, int slot,
                                        const __half* Mh, const __half* Ml,
                                        int s, int o0, int tid, bool lo)
{
    const char* srcH = (const char*)(Mh + ((size_t)s * 256 + o0) * 32);
    const char* srcL = (const char*)(Ml + ((size_t)s * 256 + o0) * 32);
    uint32_t dH = sb + MOFF + (uint32_t)slot * 2 * MSTG;
    uint32_t dL = dH + MSTG;
#pragma unroll
    for (int q = 0; q < 2; q++) {
        int g = tid * 2 + q;
        int r = g >> 2, sg = g & 3;
        uint32_t off = (uint32_t)(r * 80 + sg * 16);
        size_t so = (size_t)r * 64 + sg * 16;
        CP16(dH + off, srcH + so);
        if (lo) CP16(dL + off, srcL + so);
    }
}

__global__ __launch_bounds__(256, 1)
void conv_mma(const float* __restrict__ u, const __half* __restrict__ Mh,
              const __half* __restrict__ Ml, float* __restrict__ out)
{
    extern __shared__ char smem[];
    const uint32_t sb = smem_u32(smem);
    const int tid = threadIdx.x, lane = tid & 31, w = tid >> 5;
    const int wm = w >> 2, wn = w & 3;
    const int n0 = blockIdx.x * 128;
    const int o0 = blockIdx.y * 128;

    issue_m(sb, 0, Mh, Ml, 0, o0, tid, true); CPCOMMIT();
    issue_m(sb, 1, Mh, Ml, 1, o0, tid, true); CPCOMMIT();

    for (int i = tid; i < UROWS * 64; i += 256) {
        int r = i >> 6, c4 = i & 63;
        int n = n0 - (TAPS - 1) + r;
        float4 v = make_float4(0.f, 0.f, 0.f, 0.f);
        if (n >= 0 && n < NTOT) v = *(const float4*)(u + (size_t)n * ULEN + c4 * 4);
        uint32_t h0, l0, h1, l1;
        split2(v.x, v.y, h0, l0);
        split2(v.z, v.w, h1, l1);
        uint32_t base = (uint32_t)((r * UPITCH + c4 * 4) * 2);
        *(uint2*)(smem + base)       = make_uint2(h0, h1);
        *(uint2*)(smem + USZ + base) = make_uint2(l0, l1);
    }

    float acc[4][4][4] = {};
    const int S = TAPS * 8;
    for (int s = 0; s < S; s++) {
        if (s == S - 1) CPWAIT0(); else CPWAIT1();
        __syncthreads();
        int j = s >> 3, kc = s & 7;
        uint32_t aH = sb + (uint32_t)(((((TAPS - 1) - j) + wm * 64) * UPITCH + kc * 32) * 2);
        uint32_t aL = aH + USZ;
        uint32_t bH = sb + MOFF + (uint32_t)(s % 3) * 2 * MSTG;
        uint32_t bL = bH + MSTG;
        if (j < 2)
            compute_stage<3, 4>(aH, aL, bH, bL, lane, wn, acc, UPITCH);
        else
            compute_stage<1, 4>(aH, aL, bH, bL, lane, wn, acc, UPITCH);
        if (s + 2 < S) {
            issue_m(sb, (s + 2) % 3, Mh, Ml, s + 2, o0, tid, ((s + 2) >> 3) < 2);
            CPCOMMIT();
        }
    }
    __syncthreads();

    float* epi = (float*)smem;   // 128 x 132
#pragma unroll
    for (int mi = 0; mi < 4; mi++)
#pragma unroll
        for (int ni = 0; ni < 4; ni++) {
            int row = wm * 64 + mi * 16 + (lane >> 2);
            int col = wn * 32 + ni * 8 + ((lane & 3) << 1);
            epi[col * 132 + row]           = tanhf(acc[mi][ni][0]);
            epi[(col + 1) * 132 + row]     = tanhf(acc[mi][ni][1]);
            epi[col * 132 + row + 8]       = tanhf(acc[mi][ni][2]);
            epi[(col + 1) * 132 + row + 8] = tanhf(acc[mi][ni][3]);
        }
    __syncthreads();
    {
        int r = tid >> 1, half = tid & 1;
        float* dst = out + (size_t)(o0 + r) * NTOT + n0 + half * 64;
        const float* src = epi + r * 132 + half * 64;
#pragma unroll
        for (int i = 0; i < 16; i++)
            *(float4*)(dst + i * 4) = *(const float4*)(src + i * 4);
    }
}

// ---------------- split + transpose-split into blocked layout (coalesced) --------
__global__ void split_tr(const float* __restrict__ in, __half* oh, __half* ol,
                         __half* th, __half* tl, int R, int Cc)
{
    __shared__ float ts[32][33];
    int c0 = blockIdx.x << 5, r0 = blockIdx.y << 5;
    int lx = threadIdx.x, ly = threadIdx.y;
    int tid = ly * 32 + lx;   // 0..255
    for (int i = ly; i < 32; i += 8)
        ts[i][lx] = in[(size_t)(r0 + i) * Cc + c0 + lx];
    __syncthreads();

    if (oh && tid < 128) {
        int r = tid >> 2, ch4 = tid & 3;
        int row = r0 + r, colc = c0 + ch4 * 8;
        uint32_t h[4], l[4];
#pragma unroll
        for (int e = 0; e < 4; e++)
            split2(ts[r][ch4 * 8 + 2 * e], ts[r][ch4 * 8 + 2 * e + 1], h[e], l[e]);
        size_t off = ((size_t)(row >> 7) * (Cc >> 6) + (colc >> 6)) * 8192 +
                     (size_t)(row & 127) * 64 + ((((colc >> 3) & 7) ^ (row & 7)) << 3);
        *(uint4*)(oh + off) = make_uint4(h[0], h[1], h[2], h[3]);
        *(uint4*)(ol + off) = make_uint4(l[0], l[1], l[2], l[3]);
    }
    if (th && tid >= 128) {
        int t2 = tid - 128;
        int r = t2 >> 2, ch4 = t2 & 3;
        int row = c0 + r, colc = r0 + ch4 * 8;
        uint32_t h[4], l[4];
#pragma unroll
        for (int e = 0; e < 4; e++)
            split2(ts[ch4 * 8 + 2 * e][r], ts[ch4 * 8 + 2 * e + 1][r], h[e], l[e]);
        size_t off = ((size_t)(row >> 7) * (R >> 6) + (colc >> 6)) * 8192 +
                     (size_t)(row & 127) * 64 + ((((colc >> 3) & 7) ^ (row & 7)) << 3);
        *(uint4*)(th + off) = make_uint4(h[0], h[1], h[2], h[3]);
        *(uint4*)(tl + off) = make_uint4(l[0], l[1], l[2], l[3]);
    }
}

__global__ void build_mtb(const float* __restrict__ Mall, const float* __restrict__ D,
                          __half* __restrict__ Mh, __half* __restrict__ Ml)
{
    int idx = blockIdx.x * 256 + threadIdx.x;
    int k = idx & 255, o = (idx >> 8) & 255, j = idx >> 16;
    float v = Mall[(size_t)((j << 8) + o) * ULEN + k];
    if (j == 0) v += D[(o << 8) + k];
    __half h = __float2half_rn(v);
    __half l = __float2half_rn(v - __half2float(h));
    int kc = k >> 5, ki = k & 31;
    size_t dst = ((size_t)(j * 8 + kc) * 256 + o) * 32 + ki;
    Mh[dst] = h;
    Ml[dst] = l;
}

// ---------------- launcher ----------------
extern "C" void kernel_launch(void* const* d_in, const int* in_sizes, int n_in,
                              void* d_out, int out_size)
{
    const float* u  = (const float*)d_in[0];
    const float* A  = (const float*)d_in[1];
    const float* B  = (const float*)d_in[2];
    const float* Cm = (const float*)d_in[3];
    const float* D  = (const float*)d_in[4];

    __half *Ah, *Al, *Ath, *Atl, *S2h, *S2l, *St2h, *St2l, *S4h, *S4l, *St4h, *St4l;
    __half *St8h, *St8l, *Ph, *Pl, *Bth, *Btl, *Mhi, *Mlo;
    float *Mall;
    void* syncp;
    cudaGetSymbolAddress((void**)&Ah,   g_Ah);   cudaGetSymbolAddress((void**)&Al,   g_Al);
    cudaGetSymbolAddress((void**)&Ath,  g_Ath);  cudaGetSymbolAddress((void**)&Atl,  g_Atl);
    cudaGetSymbolAddress((void**)&S2h,  g_S2h);  cudaGetSymbolAddress((void**)&S2l,  g_S2l);
    cudaGetSymbolAddress((void**)&St2h, g_St2h); cudaGetSymbolAddress((void**)&St2l, g_St2l);
    cudaGetSymbolAddress((void**)&S4h,  g_S4h);  cudaGetSymbolAddress((void**)&S4l,  g_S4l);
    cudaGetSymbolAddress((void**)&St4h, g_St4h); cudaGetSymbolAddress((void**)&St4l, g_St4l);
    cudaGetSymbolAddress((void**)&St8h, g_St8h); cudaGetSymbolAddress((void**)&St8l, g_St8l);
    cudaGetSymbolAddress((void**)&Ph,   g_Ph);   cudaGetSymbolAddress((void**)&Pl,   g_Pl);
    cudaGetSymbolAddress((void**)&Bth,  g_Bth);  cudaGetSymbolAddress((void**)&Btl,  g_Btl);
    cudaGetSymbolAddress((void**)&Mall, g_Mall);
    cudaGetSymbolAddress((void**)&Mhi,  g_Mhi);  cudaGetSymbolAddress((void**)&Mlo,  g_Mlo);
    cudaGetSymbolAddress(&syncp, g_sync);

    cudaFuncSetAttribute(conv_mma,   cudaFuncAttributeMaxDynamicSharedMemorySize, CONV_SMEM);
    cudaFuncSetAttribute(chain_pers, cudaFuncAttributeMaxDynamicSharedMemorySize, GEMM_SMEM);

    split_tr<<<dim3(32, 32), dim3(32, 8)>>>(A,  Ah, Al, Ath, Atl, XLEN, XLEN);
    split_tr<<<dim3(32, 8),  dim3(32, 8)>>>(Cm, Ph, Pl, nullptr, nullptr, YLEN, XLEN);
    split_tr<<<dim3(8, 32),  dim3(32, 8)>>>(B,  nullptr, nullptr, Bth, Btl, XLEN, ULEN);

    cudaMemsetAsync(syncp, 0, sizeof(unsigned));

    JobList jl = {{
        // r1: S2 (+St2) = A@A [1p];  P1 = C@A [3p]
        {Ah, Al, Ath, Atl, S2h, S2l, St2h, St2l, nullptr, 8, 8, 0, 1, 1},
        {Ph, Pl, Ath, Atl, Ph + PJH, Pl + PJH, nullptr, nullptr, nullptr, 2, 8, 0, 3, 1},
        // r2: S4 (+St4) = S2@S2 [1p];  P[2:4] = P[0:2]@A2 [1p]
        {S2h, S2l, St2h, St2l, S4h, S4l, St4h, St4l, nullptr, 8, 8, 0, 1, 2},
        {Ph, Pl, St2h, St2l, Ph + 2 * PJH, Pl + 2 * PJH, nullptr, nullptr, nullptr, 4, 8, 0, 1, 2},
        // r3: St8 = (S4@S4)^T [1p];  P[4:8] = P[0:4]@A4 [1p];  Mall[0:2] = P[0:2]@B [3p]
        {S4h, S4l, St4h, St4l, nullptr, nullptr, St8h, St8l, nullptr, 8, 8, 0, 1, 3},
        {Ph, Pl, St4h, St4l, Ph + 4 * PJH, Pl + 4 * PJH, nullptr, nullptr, nullptr, 8, 8, 0, 1, 3},
        {Ph, Pl, Bth, Btl, nullptr, nullptr, nullptr, nullptr, Mall, 4, 2, ULEN, 3, 3},
        // r4: P[8:16] = P[0:8]@A8 [1p];  Mall[2:8] = P[2:8]@B [1p]
        {Ph, Pl, St8h, St8l, Ph + 8 * PJH, Pl + 8 * PJH, nullptr, nullptr, nullptr, 16, 8, 0, 1, 4},
        {Ph + 2 * PJH, Pl + 2 * PJH, Bth, Btl, nullptr, nullptr, nullptr, nullptr,
         Mall + 2 * YLEN * ULEN, 12, 2, ULEN, 1, 4},
        // r5: Mall[8:16] = P[8:16]@B [1p]
        {Ph + 8 * PJH, Pl + 8 * PJH, Bth, Btl, nullptr, nullptr, nullptr, nullptr,
         Mall + 8 * YLEN * ULEN, 16, 2, ULEN, 1, 5},
    }};

    chain_pers<<<NB, 512, GEMM_SMEM>>>(jl);

    build_mtb<<<(TAPS * YLEN * ULEN) / 256, 256>>>(Mall, D, Mhi, Mlo);

    conv_mma<<<dim3(NTOT / 128, 2), 256, CONV_SMEM>>>(u, Mhi, Mlo, (float*)d_out);
}